// round 13
// baseline (speedup 1.0000x reference)
#include <cuda_runtime.h>
#include <cuda_bf16.h>
#include <math.h>
#include <stdint.h>

#define NN    8192
#define NFEAT 512
#define NHID  256
#define NCLS  2
#define ALPHA 0.5f

// ---------------- scratch (device globals; no allocation allowed) ----------
struct Scratch {
    float rowsum[NN];
    float colsum[NN];
    float M  [NN * NHID];        // x @ W1  (tf32)
    float Y1a[NN * NHID];        // DAD @ M        (K first half)
    float Y1b[NN * NHID];        // DAD @ M        (K second half)
    float Y2a[NN * NHID];        // DAD @ Y1
    float Y2b[NN * NHID];
    float V [NN * NCLS];
    float Z1[NN * NCLS];
    float Z2[NN * NCLS];
};
__device__ Scratch g_s;
__device__ __align__(16) __nv_bfloat16 g_adjb[(size_t)NN * NN];  // bf16 adj
__device__ __align__(16) __nv_bfloat16 g_Bb[(size_t)NHID * NN];  // B^T operand (n-major)

// ---------------- PTX helpers ----------------------------------------------
__device__ __forceinline__ float to_tf32(float x) {
    float y;
    asm("cvt.rna.tf32.f32 %0, %1;" : "=f"(y) : "f"(x));
    return y;
}

__device__ __forceinline__ void cp_async16(uint32_t saddr, const void* gsrc) {
    asm volatile("cp.async.cg.shared.global [%0], [%1], 16;\n" :: "r"(saddr), "l"(gsrc));
}
#define CP_COMMIT()  asm volatile("cp.async.commit_group;\n" ::: "memory")
#define CP_WAIT(n)   asm volatile("cp.async.wait_group %0;\n" :: "n"(n) : "memory")

__device__ __forceinline__ void ldsm4(uint32_t& r0, uint32_t& r1, uint32_t& r2,
                                      uint32_t& r3, uint32_t addr) {
    asm volatile("ldmatrix.sync.aligned.m8n8.x4.shared.b16 {%0,%1,%2,%3}, [%4];"
                 : "=r"(r0), "=r"(r1), "=r"(r2), "=r"(r3) : "r"(addr));
}

__device__ __forceinline__ void mma_bf16(float* d, const uint32_t* a, const uint32_t* b) {
    asm volatile(
        "mma.sync.aligned.m16n8k16.row.col.f32.bf16.bf16.f32 "
        "{%0,%1,%2,%3}, {%4,%5,%6,%7}, {%8,%9}, {%0,%1,%2,%3};"
        : "+f"(d[0]), "+f"(d[1]), "+f"(d[2]), "+f"(d[3])
        : "r"(a[0]), "r"(a[1]), "r"(a[2]), "r"(a[3]), "r"(b[0]), "r"(b[1]));
}

__device__ __forceinline__ void mma_tf32(float* d, const float* a, const float* b) {
    uint32_t a0 = __float_as_uint(a[0]), a1 = __float_as_uint(a[1]);
    uint32_t a2 = __float_as_uint(a[2]), a3 = __float_as_uint(a[3]);
    uint32_t b0 = __float_as_uint(b[0]), b1 = __float_as_uint(b[1]);
    asm volatile(
        "mma.sync.aligned.m16n8k8.row.col.f32.tf32.tf32.f32 "
        "{%0,%1,%2,%3}, {%4,%5,%6,%7}, {%8,%9}, {%0,%1,%2,%3};"
        : "+f"(d[0]), "+f"(d[1]), "+f"(d[2]), "+f"(d[3])
        : "r"(a0), "r"(a1), "r"(a2), "r"(a3), "r"(b0), "r"(b1));
}

__device__ __forceinline__ float inv_sqrt_pos(float v) {
    return (v > 0.0f) ? rsqrtf(v) : 0.0f;
}

// ---------------- utility ----------------------------------------------------
__global__ void k_zero(float* __restrict__ p, int n) {
    int i = blockIdx.x * blockDim.x + threadIdx.x;
    if (i < n) p[i] = 0.0f;
}

// ---------------- degree sums + bf16 conversion (single pass over adj) ------
// 4-row batching: 4 independent float4 loads are issued before the serializing
// shuffle-reduce, raising MLP.
__global__ void __launch_bounds__(256) k_sums_cvt(const float* __restrict__ adj,
                                                  __nv_bfloat16* __restrict__ adjb,
                                                  float* __restrict__ rowsum,
                                                  float* __restrict__ colsum) {
    int lane = threadIdx.x & 31;
    int c0 = blockIdx.x * 1024 + threadIdx.x * 4;
    size_t r0 = (size_t)blockIdx.y * 128;
    float c4[4] = {0, 0, 0, 0};
    for (int r = 0; r < 128; r += 4) {
        float4 v[4];
#pragma unroll
        for (int u = 0; u < 4; u++)
            v[u] = *(const float4*)(adj + (r0 + r + u) * NN + c0);
#pragma unroll
        for (int u = 0; u < 4; u++) {
            c4[0] += v[u].x; c4[1] += v[u].y; c4[2] += v[u].z; c4[3] += v[u].w;
            __nv_bfloat162 p0 = __floats2bfloat162_rn(v[u].x, v[u].y);
            __nv_bfloat162 p1 = __floats2bfloat162_rn(v[u].z, v[u].w);
            uint2 pk;
            pk.x = *reinterpret_cast<uint32_t*>(&p0);
            pk.y = *reinterpret_cast<uint32_t*>(&p1);
            *reinterpret_cast<uint2*>(adjb + (r0 + r + u) * NN + c0) = pk;
        }
#pragma unroll
        for (int u = 0; u < 4; u++) {
            float w = v[u].x + v[u].y + v[u].z + v[u].w;
#pragma unroll
            for (int o = 16; o > 0; o >>= 1) w += __shfl_down_sync(0xffffffffu, w, o);
            if (lane == 0) atomicAdd(&rowsum[r0 + r + u], w);
        }
    }
#pragma unroll
    for (int q = 0; q < 4; q++) atomicAdd(&colsum[c0 + q], c4[q]);
}

// ---------------- operand prep: (src1 [+ src2]) * dcol -> transpose -> bf16 --
__global__ void __launch_bounds__(256) k_transpose_bf(const float* __restrict__ src,
                                                      const float* __restrict__ src2,
                                                      __nv_bfloat16* __restrict__ dst,
                                                      int R, int Cc,
                                                      const float* __restrict__ colsum) {
    __shared__ float t[32][33];
    int r0 = blockIdx.y * 32;
    int c0 = blockIdx.x * 32;
    int x = threadIdx.x & 31;
    int y = threadIdx.x >> 5;
#pragma unroll
    for (int j = 0; j < 32; j += 8) {
        int r = r0 + y + j;
        size_t idx = (size_t)r * Cc + c0 + x;
        float val = src[idx];
        if (src2) val += src2[idx];
        t[y + j][x] = val * inv_sqrt_pos(colsum[r]);
    }
    __syncthreads();
#pragma unroll
    for (int j = 0; j < 32; j += 8) {
        int c = c0 + y + j;
        dst[(size_t)c * R + r0 + x] = __float2bfloat16_rn(t[x][y + j]);
    }
}

// ---------------- bf16 tensor-core GEMM, K-split ----------------------------
// A: [8192 x Kfull] bf16; B: [256 x Kfull] bf16 (already B^T).
// blockIdx.z selects the K half; half-z writes Cz (fp32, 8192x256).
// Tile 64x128, BK=32, 8 warps (2x4), 4-stage cp.async.
#define GBK 32
#define ROWB 80
#define G_NROWS 192
#define G_STAGE (G_NROWS * ROWB)      // 15360
#define G_SMEM (4 * G_STAGE)          // 61440

__global__ void __launch_bounds__(256)
k_bf16_gemm(const __nv_bfloat16* __restrict__ A, const __nv_bfloat16* __restrict__ B,
            float* __restrict__ C0, float* __restrict__ C1,
            const float* __restrict__ rowsum, int Kfull) {
    extern __shared__ char smem[];
    uint32_t sb = (uint32_t)__cvta_generic_to_shared(smem);
    int tid = threadIdx.x;
    int w = tid >> 5, lane = tid & 31;
    int wm0 = (w >> 2) * 32;
    int wn0 = (w & 3) * 32;
    int bx = blockIdx.x, by = blockIdx.y, bz = blockIdx.z;

    int Klen = Kfull >> 1;
    const __nv_bfloat16* Ag = A + (size_t)by * 64 * Kfull + (size_t)bz * Klen;
    const __nv_bfloat16* Bg = B + (size_t)bx * 128 * Kfull + (size_t)bz * Klen;
    float* C = bz ? C1 : C0;

    float acc[2][4][4];
#pragma unroll
    for (int mt = 0; mt < 2; mt++)
#pragma unroll
        for (int nt = 0; nt < 4; nt++)
#pragma unroll
            for (int f = 0; f < 4; f++) acc[mt][nt][f] = 0.0f;

    auto load_stage = [&](int buf, int k0) {
        uint32_t base = sb + buf * G_STAGE;
#pragma unroll
        for (int j = 0; j < 3; j++) {
            int idx = j * 256 + tid;
            int row = idx >> 2;
            int ch = idx & 3;
            const __nv_bfloat16* g =
                (row < 64 ? Ag + (size_t)row * Kfull
                          : Bg + (size_t)(row - 64) * Kfull)
                + k0 + ch * 8;
            cp_async16(base + row * ROWB + ch * 16, g);
        }
    };

    int nK = Klen / GBK;
    load_stage(0, 0); CP_COMMIT();
    load_stage(1, GBK); CP_COMMIT();
    load_stage(2, 2 * GBK); CP_COMMIT();

#pragma unroll 1
    for (int i = 0; i < nK; i++) {
        CP_WAIT(2);
        __syncthreads();
        if (i + 3 < nK) load_stage((i + 3) & 3, (i + 3) * GBK);
        CP_COMMIT();

        uint32_t sA = sb + (i & 3) * G_STAGE;
        uint32_t sB = sA + 64 * ROWB;
#pragma unroll
        for (int ks = 0; ks < 2; ks++) {
            int kc = ks * 2;
            uint32_t a[2][4];
#pragma unroll
            for (int mt = 0; mt < 2; mt++) {
                uint32_t addr = sA + (wm0 + mt * 16 + (lane & 15)) * ROWB
                              + (kc + (lane >> 4)) * 16;
                ldsm4(a[mt][0], a[mt][1], a[mt][2], a[mt][3], addr);
            }
            uint32_t bfr[4][2];
#pragma unroll
            for (int j = 0; j < 2; j++) {
                uint32_t addr = sB
                    + (wn0 + j * 16 + (lane & 7) + ((lane >> 4) << 3)) * ROWB
                    + (kc + ((lane >> 3) & 1)) * 16;
                uint32_t r0, r1, r2, r3;
                ldsm4(r0, r1, r2, r3, addr);
                bfr[2 * j][0] = r0; bfr[2 * j][1] = r1;
                bfr[2 * j + 1][0] = r2; bfr[2 * j + 1][1] = r3;
            }
#pragma unroll
            for (int mt = 0; mt < 2; mt++)
#pragma unroll
                for (int nt = 0; nt < 4; nt++)
                    mma_bf16(acc[mt][nt], a[mt], bfr[nt]);
        }
    }

    int g = lane >> 2, q = lane & 3;
#pragma unroll
    for (int mt = 0; mt < 2; mt++) {
        int r0 = by * 64 + wm0 + mt * 16 + g;
        float rs0 = inv_sqrt_pos(rowsum[r0]);
        float rs1 = inv_sqrt_pos(rowsum[r0 + 8]);
#pragma unroll
        for (int nt = 0; nt < 4; nt++) {
            int cc = bx * 128 + wn0 + nt * 8 + 2 * q;
            float2 v0 = make_float2(acc[mt][nt][0] * rs0, acc[mt][nt][1] * rs0);
            float2 v1 = make_float2(acc[mt][nt][2] * rs1, acc[mt][nt][3] * rs1);
            *(float2*)(C + (size_t)r0 * NHID + cc) = v0;
            *(float2*)(C + (size_t)(r0 + 8) * NHID + cc) = v1;
        }
    }
}

// ---------------- tf32 tensor-core GEMM (x @ W1; R7-validated) --------------
#define MT_BK 16
#define AS_STRIDE 20
#define BS_STRIDE 136

__global__ void __launch_bounds__(128) k_mma_tf32(const float* __restrict__ A,
                                                  const float* __restrict__ B,
                                                  float* __restrict__ C,
                                                  int K) {
    __shared__ float As[2][128 * AS_STRIDE];
    __shared__ float Bs[2][MT_BK * BS_STRIDE];

    int tid = threadIdx.x;
    int wid = tid >> 5, lane = tid & 31;
    int wm0 = (wid >> 1) * 64;
    int wn0 = (wid & 1) * 64;
    int bx = blockIdx.x, by = blockIdx.y;

    const float* Ag = A + (size_t)by * 128 * K;
    const float* Bg = B + (size_t)bx * 128;

    float acc[4][8][4];
#pragma unroll
    for (int mt = 0; mt < 4; mt++)
#pragma unroll
        for (int nt = 0; nt < 8; nt++)
#pragma unroll
            for (int f = 0; f < 4; f++) acc[mt][nt][f] = 0.0f;

    int g = lane >> 2;
    int q = lane & 3;

    auto loadA = [&](int buf, int k0) {
#pragma unroll
        for (int i = 0; i < 4; i++) {
            int c = i * 128 + tid;
            int row = c >> 2;
            int coff = (c & 3) * 4;
            uint32_t s = (uint32_t)__cvta_generic_to_shared(
                &As[buf][row * AS_STRIDE + coff]);
            cp_async16(s, Ag + (size_t)row * K + k0 + coff);
        }
    };
    auto loadB = [&](int buf, int k0) {
#pragma unroll
        for (int i = 0; i < 4; i++) {
            int c = i * 128 + tid;
            int kr = c >> 5;
            int coff = (c & 31) * 4;
            uint32_t s = (uint32_t)__cvta_generic_to_shared(
                &Bs[buf][kr * BS_STRIDE + coff]);
            cp_async16(s, Bg + (size_t)(k0 + kr) * NHID + coff);
        }
    };

    loadA(0, 0);
    loadB(0, 0);
    CP_COMMIT();

    int buf = 0;
#pragma unroll 1
    for (int k0 = 0; k0 < K; k0 += MT_BK) {
        if (k0 + MT_BK < K) {
            loadA(buf ^ 1, k0 + MT_BK);
            loadB(buf ^ 1, k0 + MT_BK);
            CP_COMMIT();
            CP_WAIT(1);
        } else {
            CP_WAIT(0);
        }
        __syncthreads();

#pragma unroll
        for (int ks = 0; ks < 2; ks++) {
            int kb = ks * 8;
            float afr[4][4];
#pragma unroll
            for (int mt = 0; mt < 4; mt++) {
                int r = wm0 + mt * 16 + g;
                afr[mt][0] = to_tf32(As[buf][r * AS_STRIDE + kb + q]);
                afr[mt][1] = to_tf32(As[buf][(r + 8) * AS_STRIDE + kb + q]);
                afr[mt][2] = to_tf32(As[buf][r * AS_STRIDE + kb + q + 4]);
                afr[mt][3] = to_tf32(As[buf][(r + 8) * AS_STRIDE + kb + q + 4]);
            }
            float bfr[8][2];
#pragma unroll
            for (int nt = 0; nt < 8; nt++) {
                int col = wn0 + nt * 8 + g;
                bfr[nt][0] = to_tf32(Bs[buf][(kb + q) * BS_STRIDE + col]);
                bfr[nt][1] = to_tf32(Bs[buf][(kb + q + 4) * BS_STRIDE + col]);
            }
#pragma unroll
            for (int mt = 0; mt < 4; mt++)
#pragma unroll
                for (int nt = 0; nt < 8; nt++)
                    mma_tf32(acc[mt][nt], afr[mt], bfr[nt]);
        }
        __syncthreads();
        buf ^= 1;
    }

#pragma unroll
    for (int mt = 0; mt < 4; mt++) {
        int r0 = by * 128 + wm0 + mt * 16 + g;
#pragma unroll
        for (int nt = 0; nt < 8; nt++) {
            int cc = bx * 128 + wn0 + nt * 8 + q * 2;
            float2 v0 = make_float2(acc[mt][nt][0], acc[mt][nt][1]);
            float2 v1 = make_float2(acc[mt][nt][2], acc[mt][nt][3]);
            *(float2*)(C + (size_t)r0 * NHID + cc) = v0;
            *(float2*)(C + (size_t)(r0 + 8) * NHID + cc) = v1;
        }
    }
}

// ---------------- fused H + H@W2  (one warp per row; K-split sums) -----------
__global__ void __launch_bounds__(256) k_combineV(const float* __restrict__ M,
                                                  const float* __restrict__ Y1a,
                                                  const float* __restrict__ Y1b,
                                                  const float* __restrict__ Y2a,
                                                  const float* __restrict__ Y2b,
                                                  const float* __restrict__ W2,
                                                  float* __restrict__ V) {
    int warp = threadIdx.x >> 5;
    int lane = threadIdx.x & 31;
    int row = blockIdx.x * 8 + warp;
    size_t off = (size_t)row * NHID;
    float a0 = 0.0f, a1 = 0.0f;
#pragma unroll
    for (int j = lane; j < NHID; j += 32) {
        float y1 = Y1a[off + j] + Y1b[off + j];
        float y2 = Y2a[off + j] + Y2b[off + j];
        float h = fmaxf(ALPHA * M[off + j] + (ALPHA - 1.0f) * y1 - y2, 0.0f);
        a0 = fmaf(h, __ldg(&W2[2 * j + 0]), a0);
        a1 = fmaf(h, __ldg(&W2[2 * j + 1]), a1);
    }
#pragma unroll
    for (int o = 16; o > 0; o >>= 1) {
        a0 += __shfl_down_sync(0xffffffffu, a0, o);
        a1 += __shfl_down_sync(0xffffffffu, a1, o);
    }
    if (lane == 0) {
        V[2 * row + 0] = a0;
        V[2 * row + 1] = a1;
    }
}

// ---------------- adj(bf16) width-2 matvec (MLP-batched) ---------------------
__global__ void __launch_bounds__(256) k_adjmv2_bf(const __nv_bfloat16* __restrict__ adjb,
                                                   const float* __restrict__ v,
                                                   const float* __restrict__ rowsum,
                                                   const float* __restrict__ colsum,
                                                   float* __restrict__ out) {
    int row = blockIdx.x;
    const __nv_bfloat16* a = adjb + (size_t)row * NN;
    float a0 = 0.0f, a1 = 0.0f;
    for (int j = threadIdx.x * 16; j < NN; j += 256 * 16) {
        uint4 pk0 = *(const uint4*)(a + j);
        uint4 pk1 = *(const uint4*)(a + j + 8);
        float4 cs[4];
        cs[0] = *(const float4*)(colsum + j);
        cs[1] = *(const float4*)(colsum + j + 4);
        cs[2] = *(const float4*)(colsum + j + 8);
        cs[3] = *(const float4*)(colsum + j + 12);
        float fv[16];
        {
            float2 f0 = __bfloat1622float2(*reinterpret_cast<__nv_bfloat162*>(&pk0.x));
            float2 f1 = __bfloat1622float2(*reinterpret_cast<__nv_bfloat162*>(&pk0.y));
            float2 f2 = __bfloat1622float2(*reinterpret_cast<__nv_bfloat162*>(&pk0.z));
            float2 f3 = __bfloat1622float2(*reinterpret_cast<__nv_bfloat162*>(&pk0.w));
            fv[0] = f0.x; fv[1] = f0.y; fv[2] = f1.x; fv[3] = f1.y;
            fv[4] = f2.x; fv[5] = f2.y; fv[6] = f3.x; fv[7] = f3.y;
            float2 g0 = __bfloat1622float2(*reinterpret_cast<__nv_bfloat162*>(&pk1.x));
            float2 g1 = __bfloat1622float2(*reinterpret_cast<__nv_bfloat162*>(&pk1.y));
            float2 g2 = __bfloat1622float2(*reinterpret_cast<__nv_bfloat162*>(&pk1.z));
            float2 g3 = __bfloat1622float2(*reinterpret_cast<__nv_bfloat162*>(&pk1.w));
            fv[8] = g0.x; fv[9] = g0.y; fv[10] = g1.x; fv[11] = g1.y;
            fv[12] = g2.x; fv[13] = g2.y; fv[14] = g3.x; fv[15] = g3.y;
        }
        const float* csf = reinterpret_cast<const float*>(cs);
#pragma unroll
        for (int t = 0; t < 16; t++) {
            float av = fv[t] * inv_sqrt_pos(csf[t]);
            a0 = fmaf(av, v[2 * (j + t) + 0], a0);
            a1 = fmaf(av, v[2 * (j + t) + 1], a1);
        }
    }
    __shared__ float s0[256];
    __shared__ float s1[256];
    s0[threadIdx.x] = a0;
    s1[threadIdx.x] = a1;
    __syncthreads();
    for (int st = 128; st > 0; st >>= 1) {
        if (threadIdx.x < st) {
            s0[threadIdx.x] += s0[threadIdx.x + st];
            s1[threadIdx.x] += s1[threadIdx.x + st];
        }
        __syncthreads();
    }
    if (threadIdx.x == 0) {
        float r = inv_sqrt_pos(rowsum[row]);
        out[2 * row + 0] = r * s0[0];
        out[2 * row + 1] = r * s1[0];
    }
}

__global__ void k_final(const float* __restrict__ V, const float* __restrict__ Z1,
                        const float* __restrict__ Z2, const float* __restrict__ b2,
                        float* __restrict__ out) {
    int i = blockIdx.x * blockDim.x + threadIdx.x;
    if (i < NN) {
        float l0 = ALPHA * V[2 * i + 0] + (ALPHA - 1.0f) * Z1[2 * i + 0] - Z2[2 * i + 0] + b2[0];
        float l1 = ALPHA * V[2 * i + 1] + (ALPHA - 1.0f) * Z1[2 * i + 1] - Z2[2 * i + 1] + b2[1];
        float m = fmaxf(l0, l1);
        float lse = m + logf(expf(l0 - m) + expf(l1 - m));
        out[2 * i + 0] = l0 - lse;
        out[2 * i + 1] = l1 - lse;
    }
}

// ---------------- launcher --------------------------------------------------
extern "C" void kernel_launch(void* const* d_in, const int* in_sizes, int n_in,
                              void* d_out, int out_size) {
    const float *x = nullptr, *adj = nullptr, *W1 = nullptr, *W2 = nullptr, *b2 = nullptr;
    for (int i = 0; i < n_in; i++) {
        switch (in_sizes[i]) {
            case NN * NFEAT:             x   = (const float*)d_in[i]; break;
            case (int)((size_t)NN * NN): adj = (const float*)d_in[i]; break;
            case NFEAT * NHID:           W1  = (const float*)d_in[i]; break;
            case NHID * NCLS:            W2  = (const float*)d_in[i]; break;
            case NCLS:                   b2  = (const float*)d_in[i]; break;
        }
    }
    float* out = (float*)d_out;

    Scratch* s = nullptr;
    cudaGetSymbolAddress((void**)&s, g_s);
    __nv_bfloat16* adjb = nullptr;
    cudaGetSymbolAddress((void**)&adjb, g_adjb);
    __nv_bfloat16* Bb = nullptr;
    cudaGetSymbolAddress((void**)&Bb, g_Bb);

    cudaFuncSetAttribute(k_bf16_gemm, cudaFuncAttributeMaxDynamicSharedMemorySize, G_SMEM);

    // 0-1) zero sums (two launches so the K-split GEMM lands at ncu index 5)
    k_zero<<<(NN + 255) / 256, 256>>>(s->rowsum, NN);
    k_zero<<<(NN + 255) / 256, 256>>>(s->colsum, NN);
    // 2) degree sums + bf16 adj copy (single pass over adj, 4-row MLP batching)
    k_sums_cvt<<<dim3(NN / 1024, NN / 128), 256>>>(adj, adjb, s->rowsum, s->colsum);
    // 3) M = x @ W1 (tf32 tensor cores)
    k_mma_tf32<<<dim3(2, NN / 128), 128>>>(x, W1, s->M, NFEAT);
    // 4) B operand prep (dcol fused)
    k_transpose_bf<<<dim3(NHID / 32, NN / 32), 256>>>(s->M, nullptr, Bb, NN, NHID, s->colsum);
    // 5) Y1 = DAD @ M, K-split across z  <-- ncu capture target
    k_bf16_gemm<<<dim3(2, NN / 64, 2), 256, G_SMEM>>>(adjb, Bb, s->Y1a, s->Y1b,
                                                      s->rowsum, NN);
    // 6) B operand prep for Y2 (sums the K-split halves)
    k_transpose_bf<<<dim3(NHID / 32, NN / 32), 256>>>(s->Y1a, s->Y1b, Bb, NN, NHID, s->colsum);
    // 7) Y2 = DAD @ Y1, K-split
    k_bf16_gemm<<<dim3(2, NN / 64, 2), 256, G_SMEM>>>(adjb, Bb, s->Y2a, s->Y2b,
                                                      s->rowsum, NN);
    // 8) V = relu(a*M + (a-1)*Y1 - Y2) @ W2  (fused; sums halves inline)
    k_combineV<<<NN / 8, 256>>>(s->M, s->Y1a, s->Y1b, s->Y2a, s->Y2b, W2, s->V);
    // 9-10) Z1 = DAD @ V ; Z2 = DAD @ Z1 (bf16 adj)
    k_adjmv2_bf<<<NN, 256>>>(adjb, s->V, s->rowsum, s->colsum, s->Z1);
    k_adjmv2_bf<<<NN, 256>>>(adjb, s->Z1, s->rowsum, s->colsum, s->Z2);
    // 11) logits + log_softmax
    k_final<<<(NN + 255) / 256, 256>>>(s->V, s->Z1, s->Z2, b2, out);
}

// round 14
// speedup vs baseline: 1.4860x; 1.4860x over previous
#include <cuda_runtime.h>
#include <cuda_bf16.h>
#include <math.h>
#include <stdint.h>

#define NN    8192
#define NFEAT 512
#define NHID  256
#define NCLS  2
#define ALPHA 0.5f

// ---------------- scratch (device globals; no allocation allowed) ----------
struct Scratch {
    float rowsum[NN];
    float colsum[NN];            // adjacent to rowsum (zeroed together)
    float M  [NN * NHID];        // x @ W1  (tf32)
    float Y1a[NN * NHID];        // DAD @ M   (K half 0)
    float Y1b[NN * NHID];        // DAD @ M   (K half 1)
    float Y2a[NN * NHID];        // DAD @ Y1
    float Y2b[NN * NHID];
    float V [NN * NCLS];
    float Z1[NN * NCLS];
    float Z2[NN * NCLS];
};
__device__ Scratch g_s;
__device__ __align__(16) __nv_bfloat16 g_adjb[(size_t)NN * NN];  // bf16 adj
__device__ __align__(16) __nv_bfloat16 g_Bb[(size_t)NHID * NN];  // B^T operand (n-major)

// ---------------- PTX helpers ----------------------------------------------
__device__ __forceinline__ float to_tf32(float x) {
    float y;
    asm("cvt.rna.tf32.f32 %0, %1;" : "=f"(y) : "f"(x));
    return y;
}

__device__ __forceinline__ void cp_async16(uint32_t saddr, const void* gsrc) {
    asm volatile("cp.async.cg.shared.global [%0], [%1], 16;\n" :: "r"(saddr), "l"(gsrc));
}
#define CP_COMMIT()  asm volatile("cp.async.commit_group;\n" ::: "memory")
#define CP_WAIT(n)   asm volatile("cp.async.wait_group %0;\n" :: "n"(n) : "memory")

__device__ __forceinline__ void ldsm4(uint32_t& r0, uint32_t& r1, uint32_t& r2,
                                      uint32_t& r3, uint32_t addr) {
    asm volatile("ldmatrix.sync.aligned.m8n8.x4.shared.b16 {%0,%1,%2,%3}, [%4];"
                 : "=r"(r0), "=r"(r1), "=r"(r2), "=r"(r3) : "r"(addr));
}

__device__ __forceinline__ void mma_bf16(float* d, const uint32_t* a, const uint32_t* b) {
    asm volatile(
        "mma.sync.aligned.m16n8k16.row.col.f32.bf16.bf16.f32 "
        "{%0,%1,%2,%3}, {%4,%5,%6,%7}, {%8,%9}, {%0,%1,%2,%3};"
        : "+f"(d[0]), "+f"(d[1]), "+f"(d[2]), "+f"(d[3])
        : "r"(a[0]), "r"(a[1]), "r"(a[2]), "r"(a[3]), "r"(b[0]), "r"(b[1]));
}

__device__ __forceinline__ void mma_tf32(float* d, const float* a, const float* b) {
    uint32_t a0 = __float_as_uint(a[0]), a1 = __float_as_uint(a[1]);
    uint32_t a2 = __float_as_uint(a[2]), a3 = __float_as_uint(a[3]);
    uint32_t b0 = __float_as_uint(b[0]), b1 = __float_as_uint(b[1]);
    asm volatile(
        "mma.sync.aligned.m16n8k8.row.col.f32.tf32.tf32.f32 "
        "{%0,%1,%2,%3}, {%4,%5,%6,%7}, {%8,%9}, {%0,%1,%2,%3};"
        : "+f"(d[0]), "+f"(d[1]), "+f"(d[2]), "+f"(d[3])
        : "r"(a0), "r"(a1), "r"(a2), "r"(a3), "r"(b0), "r"(b1));
}

__device__ __forceinline__ float inv_sqrt_pos(float v) {
    return (v > 0.0f) ? rsqrtf(v) : 0.0f;
}

// ---------------- utility ----------------------------------------------------
__global__ void k_zero(float* __restrict__ p, int n) {
    int i = blockIdx.x * blockDim.x + threadIdx.x;
    if (i < n) p[i] = 0.0f;
}

// ---------------- degree sums + bf16 conversion (R7 version, unbatched) ------
__global__ void __launch_bounds__(256) k_sums_cvt(const float* __restrict__ adj,
                                                  __nv_bfloat16* __restrict__ adjb,
                                                  float* __restrict__ rowsum,
                                                  float* __restrict__ colsum) {
    int lane = threadIdx.x & 31;
    int c0 = blockIdx.x * 1024 + threadIdx.x * 4;
    size_t r0 = (size_t)blockIdx.y * 128;
    float c4[4] = {0, 0, 0, 0};
    for (int r = 0; r < 128; r++) {
        size_t idx = (r0 + r) * NN + c0;
        float4 v = *(const float4*)(adj + idx);
        c4[0] += v.x; c4[1] += v.y; c4[2] += v.z; c4[3] += v.w;
        __nv_bfloat162 p0 = __floats2bfloat162_rn(v.x, v.y);
        __nv_bfloat162 p1 = __floats2bfloat162_rn(v.z, v.w);
        uint2 pk;
        pk.x = *reinterpret_cast<uint32_t*>(&p0);
        pk.y = *reinterpret_cast<uint32_t*>(&p1);
        *reinterpret_cast<uint2*>(adjb + idx) = pk;
        float w = v.x + v.y + v.z + v.w;
#pragma unroll
        for (int o = 16; o > 0; o >>= 1) w += __shfl_down_sync(0xffffffffu, w, o);
        if (lane == 0) atomicAdd(&rowsum[r0 + r], w);
    }
#pragma unroll
    for (int q = 0; q < 4; q++) atomicAdd(&colsum[c0 + q], c4[q]);
}

// ---------------- operand prep: (src1 [+ src2]) * dcol -> transpose -> bf16 --
__global__ void __launch_bounds__(256) k_transpose_bf(const float* __restrict__ src,
                                                      const float* __restrict__ src2,
                                                      __nv_bfloat16* __restrict__ dst,
                                                      int R, int Cc,
                                                      const float* __restrict__ colsum) {
    __shared__ float t[32][33];
    int r0 = blockIdx.y * 32;
    int c0 = blockIdx.x * 32;
    int x = threadIdx.x & 31;
    int y = threadIdx.x >> 5;
#pragma unroll
    for (int j = 0; j < 32; j += 8) {
        int r = r0 + y + j;
        size_t idx = (size_t)r * Cc + c0 + x;
        float val = src[idx];
        if (src2) val += src2[idx];
        t[y + j][x] = val * inv_sqrt_pos(colsum[r]);
    }
    __syncthreads();
#pragma unroll
    for (int j = 0; j < 32; j += 8) {
        int c = c0 + y + j;
        dst[(size_t)c * R + r0 + x] = __float2bfloat16_rn(t[x][y + j]);
    }
}

// ---------------- bf16 tensor-core GEMM, single-wave K-split -----------------
// A: [8192 x Kfull] bf16; B: [256 x Kfull] bf16 (already B^T).
// blockIdx.z selects the K half; half-z writes Cz (fp32, 8192x256).
// Tile 64x128, BK=32, 8 warps (2x4), 3-stage cp.async.
// 3 stages => smem 46080 => 4 CTAs/SM => 592 capacity >= 512 CTAs: ONE wave.
#define GBK 32
#define ROWB 80
#define G_NROWS 192
#define G_STAGE (G_NROWS * ROWB)      // 15360
#define G_SMEM (3 * G_STAGE)          // 46080

__global__ void __launch_bounds__(256, 4)
k_bf16_gemm(const __nv_bfloat16* __restrict__ A, const __nv_bfloat16* __restrict__ B,
            float* __restrict__ C0, float* __restrict__ C1,
            const float* __restrict__ rowsum, int Kfull) {
    extern __shared__ char smem[];
    uint32_t sb = (uint32_t)__cvta_generic_to_shared(smem);
    int tid = threadIdx.x;
    int w = tid >> 5, lane = tid & 31;
    int wm0 = (w >> 2) * 32;
    int wn0 = (w & 3) * 32;
    int bx = blockIdx.x, by = blockIdx.y, bz = blockIdx.z;

    int Klen = Kfull >> 1;
    const __nv_bfloat16* Ag = A + (size_t)by * 64 * Kfull + (size_t)bz * Klen;
    const __nv_bfloat16* Bg = B + (size_t)bx * 128 * Kfull + (size_t)bz * Klen;
    float* C = bz ? C1 : C0;

    float acc[2][4][4];
#pragma unroll
    for (int mt = 0; mt < 2; mt++)
#pragma unroll
        for (int nt = 0; nt < 4; nt++)
#pragma unroll
            for (int f = 0; f < 4; f++) acc[mt][nt][f] = 0.0f;

    auto load_stage = [&](int buf, int k0) {
        uint32_t base = sb + buf * G_STAGE;
#pragma unroll
        for (int j = 0; j < 3; j++) {
            int idx = j * 256 + tid;
            int row = idx >> 2;
            int ch = idx & 3;
            const __nv_bfloat16* g =
                (row < 64 ? Ag + (size_t)row * Kfull
                          : Bg + (size_t)(row - 64) * Kfull)
                + k0 + ch * 8;
            cp_async16(base + row * ROWB + ch * 16, g);
        }
    };

    int nK = Klen / GBK;               // 128
    load_stage(0, 0); CP_COMMIT();
    load_stage(1, GBK); CP_COMMIT();

    int buf = 0;
#pragma unroll 1
    for (int i = 0; i < nK; i++) {
        CP_WAIT(1);
        __syncthreads();
        if (i + 2 < nK) load_stage((i + 2) % 3, (i + 2) * GBK);
        CP_COMMIT();      // empty group near the tail keeps the count invariant

        uint32_t sA = sb + buf * G_STAGE;
        uint32_t sB = sA + 64 * ROWB;
#pragma unroll
        for (int ks = 0; ks < 2; ks++) {
            int kc = ks * 2;
            uint32_t a[2][4];
#pragma unroll
            for (int mt = 0; mt < 2; mt++) {
                uint32_t addr = sA + (wm0 + mt * 16 + (lane & 15)) * ROWB
                              + (kc + (lane >> 4)) * 16;
                ldsm4(a[mt][0], a[mt][1], a[mt][2], a[mt][3], addr);
            }
            uint32_t bfr[4][2];
#pragma unroll
            for (int j = 0; j < 2; j++) {
                uint32_t addr = sB
                    + (wn0 + j * 16 + (lane & 7) + ((lane >> 4) << 3)) * ROWB
                    + (kc + ((lane >> 3) & 1)) * 16;
                uint32_t r0, r1, r2, r3;
                ldsm4(r0, r1, r2, r3, addr);
                bfr[2 * j][0] = r0; bfr[2 * j][1] = r1;
                bfr[2 * j + 1][0] = r2; bfr[2 * j + 1][1] = r3;
            }
#pragma unroll
            for (int mt = 0; mt < 2; mt++)
#pragma unroll
                for (int nt = 0; nt < 4; nt++)
                    mma_bf16(acc[mt][nt], a[mt], bfr[nt]);
        }
        buf = (buf + 1) % 3;
    }

    int g = lane >> 2, q = lane & 3;
#pragma unroll
    for (int mt = 0; mt < 2; mt++) {
        int r0 = by * 64 + wm0 + mt * 16 + g;
        float rs0 = inv_sqrt_pos(rowsum[r0]);
        float rs1 = inv_sqrt_pos(rowsum[r0 + 8]);
#pragma unroll
        for (int nt = 0; nt < 4; nt++) {
            int cc = bx * 128 + wn0 + nt * 8 + 2 * q;
            float2 v0 = make_float2(acc[mt][nt][0] * rs0, acc[mt][nt][1] * rs0);
            float2 v1 = make_float2(acc[mt][nt][2] * rs1, acc[mt][nt][3] * rs1);
            *(float2*)(C + (size_t)r0 * NHID + cc) = v0;
            *(float2*)(C + (size_t)(r0 + 8) * NHID + cc) = v1;
        }
    }
}

// ---------------- tf32 tensor-core GEMM (x @ W1; R7-validated) --------------
#define MT_BK 16
#define AS_STRIDE 20
#define BS_STRIDE 136

__global__ void __launch_bounds__(128) k_mma_tf32(const float* __restrict__ A,
                                                  const float* __restrict__ B,
                                                  float* __restrict__ C,
                                                  int K) {
    __shared__ float As[2][128 * AS_STRIDE];
    __shared__ float Bs[2][MT_BK * BS_STRIDE];

    int tid = threadIdx.x;
    int wid = tid >> 5, lane = tid & 31;
    int wm0 = (wid >> 1) * 64;
    int wn0 = (wid & 1) * 64;
    int bx = blockIdx.x, by = blockIdx.y;

    const float* Ag = A + (size_t)by * 128 * K;
    const float* Bg = B + (size_t)bx * 128;

    float acc[4][8][4];
#pragma unroll
    for (int mt = 0; mt < 4; mt++)
#pragma unroll
        for (int nt = 0; nt < 8; nt++)
#pragma unroll
            for (int f = 0; f < 4; f++) acc[mt][nt][f] = 0.0f;

    int g = lane >> 2;
    int q = lane & 3;

    auto loadA = [&](int buf, int k0) {
#pragma unroll
        for (int i = 0; i < 4; i++) {
            int c = i * 128 + tid;
            int row = c >> 2;
            int coff = (c & 3) * 4;
            uint32_t s = (uint32_t)__cvta_generic_to_shared(
                &As[buf][row * AS_STRIDE + coff]);
            cp_async16(s, Ag + (size_t)row * K + k0 + coff);
        }
    };
    auto loadB = [&](int buf, int k0) {
#pragma unroll
        for (int i = 0; i < 4; i++) {
            int c = i * 128 + tid;
            int kr = c >> 5;
            int coff = (c & 31) * 4;
            uint32_t s = (uint32_t)__cvta_generic_to_shared(
                &Bs[buf][kr * BS_STRIDE + coff]);
            cp_async16(s, Bg + (size_t)(k0 + kr) * NHID + coff);
        }
    };

    loadA(0, 0);
    loadB(0, 0);
    CP_COMMIT();

    int buf = 0;
#pragma unroll 1
    for (int k0 = 0; k0 < K; k0 += MT_BK) {
        if (k0 + MT_BK < K) {
            loadA(buf ^ 1, k0 + MT_BK);
            loadB(buf ^ 1, k0 + MT_BK);
            CP_COMMIT();
            CP_WAIT(1);
        } else {
            CP_WAIT(0);
        }
        __syncthreads();

#pragma unroll
        for (int ks = 0; ks < 2; ks++) {
            int kb = ks * 8;
            float afr[4][4];
#pragma unroll
            for (int mt = 0; mt < 4; mt++) {
                int r = wm0 + mt * 16 + g;
                afr[mt][0] = to_tf32(As[buf][r * AS_STRIDE + kb + q]);
                afr[mt][1] = to_tf32(As[buf][(r + 8) * AS_STRIDE + kb + q]);
                afr[mt][2] = to_tf32(As[buf][r * AS_STRIDE + kb + q + 4]);
                afr[mt][3] = to_tf32(As[buf][(r + 8) * AS_STRIDE + kb + q + 4]);
            }
            float bfr[8][2];
#pragma unroll
            for (int nt = 0; nt < 8; nt++) {
                int col = wn0 + nt * 8 + g;
                bfr[nt][0] = to_tf32(Bs[buf][(kb + q) * BS_STRIDE + col]);
                bfr[nt][1] = to_tf32(Bs[buf][(kb + q + 4) * BS_STRIDE + col]);
            }
#pragma unroll
            for (int mt = 0; mt < 4; mt++)
#pragma unroll
                for (int nt = 0; nt < 8; nt++)
                    mma_tf32(acc[mt][nt], afr[mt], bfr[nt]);
        }
        __syncthreads();
        buf ^= 1;
    }

#pragma unroll
    for (int mt = 0; mt < 4; mt++) {
        int r0 = by * 128 + wm0 + mt * 16 + g;
#pragma unroll
        for (int nt = 0; nt < 8; nt++) {
            int cc = bx * 128 + wn0 + nt * 8 + q * 2;
            float2 v0 = make_float2(acc[mt][nt][0], acc[mt][nt][1]);
            float2 v1 = make_float2(acc[mt][nt][2], acc[mt][nt][3]);
            *(float2*)(C + (size_t)r0 * NHID + cc) = v0;
            *(float2*)(C + (size_t)(r0 + 8) * NHID + cc) = v1;
        }
    }
}

// ---------------- fused H + H@W2  (one warp per row; K-split sums) -----------
__global__ void __launch_bounds__(256) k_combineV(const float* __restrict__ M,
                                                  const float* __restrict__ Y1a,
                                                  const float* __restrict__ Y1b,
                                                  const float* __restrict__ Y2a,
                                                  const float* __restrict__ Y2b,
                                                  const float* __restrict__ W2,
                                                  float* __restrict__ V) {
    int warp = threadIdx.x >> 5;
    int lane = threadIdx.x & 31;
    int row = blockIdx.x * 8 + warp;
    size_t off = (size_t)row * NHID;
    float a0 = 0.0f, a1 = 0.0f;
#pragma unroll
    for (int j = lane; j < NHID; j += 32) {
        float y1 = Y1a[off + j] + Y1b[off + j];
        float y2 = Y2a[off + j] + Y2b[off + j];
        float h = fmaxf(ALPHA * M[off + j] + (ALPHA - 1.0f) * y1 - y2, 0.0f);
        a0 = fmaf(h, __ldg(&W2[2 * j + 0]), a0);
        a1 = fmaf(h, __ldg(&W2[2 * j + 1]), a1);
    }
#pragma unroll
    for (int o = 16; o > 0; o >>= 1) {
        a0 += __shfl_down_sync(0xffffffffu, a0, o);
        a1 += __shfl_down_sync(0xffffffffu, a1, o);
    }
    if (lane == 0) {
        V[2 * row + 0] = a0;
        V[2 * row + 1] = a1;
    }
}

// ---------------- adj(bf16) width-2 matvec (R7 version) ----------------------
__global__ void __launch_bounds__(256) k_adjmv2_bf(const __nv_bfloat16* __restrict__ adjb,
                                                   const float* __restrict__ v,
                                                   const float* __restrict__ rowsum,
                                                   const float* __restrict__ colsum,
                                                   float* __restrict__ out) {
    int row = blockIdx.x;
    const __nv_bfloat16* a = adjb + (size_t)row * NN;
    float a0 = 0.0f, a1 = 0.0f;
    for (int j = threadIdx.x * 8; j < NN; j += 256 * 8) {
        uint4 pk = *(const uint4*)(a + j);
        float2 f0 = __bfloat1622float2(*reinterpret_cast<__nv_bfloat162*>(&pk.x));
        float2 f1 = __bfloat1622float2(*reinterpret_cast<__nv_bfloat162*>(&pk.y));
        float2 f2 = __bfloat1622float2(*reinterpret_cast<__nv_bfloat162*>(&pk.z));
        float2 f3 = __bfloat1622float2(*reinterpret_cast<__nv_bfloat162*>(&pk.w));
        float4 c0 = *(const float4*)(colsum + j);
        float4 c1 = *(const float4*)(colsum + j + 4);
        float av[8] = { f0.x * inv_sqrt_pos(c0.x), f0.y * inv_sqrt_pos(c0.y),
                        f1.x * inv_sqrt_pos(c0.z), f1.y * inv_sqrt_pos(c0.w),
                        f2.x * inv_sqrt_pos(c1.x), f2.y * inv_sqrt_pos(c1.y),
                        f3.x * inv_sqrt_pos(c1.z), f3.y * inv_sqrt_pos(c1.w) };
#pragma unroll
        for (int t = 0; t < 8; t++) {
            a0 = fmaf(av[t], v[2 * (j + t) + 0], a0);
            a1 = fmaf(av[t], v[2 * (j + t) + 1], a1);
        }
    }
    __shared__ float s0[256];
    __shared__ float s1[256];
    s0[threadIdx.x] = a0;
    s1[threadIdx.x] = a1;
    __syncthreads();
    for (int st = 128; st > 0; st >>= 1) {
        if (threadIdx.x < st) {
            s0[threadIdx.x] += s0[threadIdx.x + st];
            s1[threadIdx.x] += s1[threadIdx.x + st];
        }
        __syncthreads();
    }
    if (threadIdx.x == 0) {
        float r = inv_sqrt_pos(rowsum[row]);
        out[2 * row + 0] = r * s0[0];
        out[2 * row + 1] = r * s1[0];
    }
}

__global__ void k_final(const float* __restrict__ V, const float* __restrict__ Z1,
                        const float* __restrict__ Z2, const float* __restrict__ b2,
                        float* __restrict__ out) {
    int i = blockIdx.x * blockDim.x + threadIdx.x;
    if (i < NN) {
        float l0 = ALPHA * V[2 * i + 0] + (ALPHA - 1.0f) * Z1[2 * i + 0] - Z2[2 * i + 0] + b2[0];
        float l1 = ALPHA * V[2 * i + 1] + (ALPHA - 1.0f) * Z1[2 * i + 1] - Z2[2 * i + 1] + b2[1];
        float m = fmaxf(l0, l1);
        float lse = m + logf(expf(l0 - m) + expf(l1 - m));
        out[2 * i + 0] = l0 - lse;
        out[2 * i + 1] = l1 - lse;
    }
}

// ---------------- launcher --------------------------------------------------
extern "C" void kernel_launch(void* const* d_in, const int* in_sizes, int n_in,
                              void* d_out, int out_size) {
    const float *x = nullptr, *adj = nullptr, *W1 = nullptr, *W2 = nullptr, *b2 = nullptr;
    for (int i = 0; i < n_in; i++) {
        switch (in_sizes[i]) {
            case NN * NFEAT:             x   = (const float*)d_in[i]; break;
            case (int)((size_t)NN * NN): adj = (const float*)d_in[i]; break;
            case NFEAT * NHID:           W1  = (const float*)d_in[i]; break;
            case NHID * NCLS:            W2  = (const float*)d_in[i]; break;
            case NCLS:                   b2  = (const float*)d_in[i]; break;
        }
    }
    float* out = (float*)d_out;

    Scratch* s = nullptr;
    cudaGetSymbolAddress((void**)&s, g_s);
    __nv_bfloat16* adjb = nullptr;
    cudaGetSymbolAddress((void**)&adjb, g_adjb);
    __nv_bfloat16* Bb = nullptr;
    cudaGetSymbolAddress((void**)&Bb, g_Bb);

    cudaFuncSetAttribute(k_bf16_gemm, cudaFuncAttributeMaxDynamicSharedMemorySize, G_SMEM);

    // 1) zero sums
    k_zero<<<(2 * NN + 255) / 256, 256>>>(s->rowsum, 2 * NN);
    // 2) degree sums + bf16 adj copy (single pass over adj)
    k_sums_cvt<<<dim3(NN / 1024, NN / 128), 256>>>(adj, adjb, s->rowsum, s->colsum);
    // 3) M = x @ W1 (tf32 tensor cores)
    k_mma_tf32<<<dim3(2, NN / 128), 128>>>(x, W1, s->M, NFEAT);
    // 4) B operand prep (dcol fused)
    k_transpose_bf<<<dim3(NHID / 32, NN / 32), 256>>>(s->M, nullptr, Bb, NN, NHID, s->colsum);
    // 5) Y1 = DAD @ M, single-wave K-split
    k_bf16_gemm<<<dim3(2, NN / 64, 2), 256, G_SMEM>>>(adjb, Bb, s->Y1a, s->Y1b,
                                                      s->rowsum, NN);
    // 6) B operand prep for Y2 (sums the K-split halves)
    k_transpose_bf<<<dim3(NHID / 32, NN / 32), 256>>>(s->Y1a, s->Y1b, Bb, NN, NHID, s->colsum);
    // 7) Y2 = DAD @ Y1, single-wave K-split
    k_bf16_gemm<<<dim3(2, NN / 64, 2), 256, G_SMEM>>>(adjb, Bb, s->Y2a, s->Y2b,
                                                      s->rowsum, NN);
    // 8) V = relu(a*M + (a-1)*Y1 - Y2) @ W2  (fused; sums halves inline)
    k_combineV<<<NN / 8, 256>>>(s->M, s->Y1a, s->Y1b, s->Y2a, s->Y2b, W2, s->V);
    // 9-10) Z1 = DAD @ V ; Z2 = DAD @ Z1 (bf16 adj)
    k_adjmv2_bf<<<NN, 256>>>(adjb, s->V, s->rowsum, s->colsum, s->Z1);
    k_adjmv2_bf<<<NN, 256>>>(adjb, s->Z1, s->rowsum, s->colsum, s->Z2);
    // 11) logits + log_softmax
    k_final<<<(NN + 255) / 256, 256>>>(s->V, s->Z1, s->Z2, b2, out);
}